// round 13
// baseline (speedup 1.0000x reference)
#include <cuda_runtime.h>
#include <cuda_fp16.h>

// Problem constants
#define CAP_A   32
#define CAP_B   32
#define KK      3
#define PSIZE   16
#define STRIDE  2
#define OH      15
#define OW      15
#define NBATCH  2
#define NPOS    (NBATCH*OH*OW)   // 450
#define KKA     (KK*KK*CAP_A)    // 288
#define NX      (NBATCH*32*32*512)  // 1,048,576 x elements
#define EPS_SQ  1e-8f
#define CPT     9                // capsules per thread (one warp per (n,j))
#define FULL    0xffffffffu
#define W4      (KKA*CAP_B*4)    // 36864 float4s in w
#define X4      (NX/4)           // 262144 float4s in x

typedef unsigned long long u64;

// ---- packed f32x2 primitives (Blackwell sm_103a) ----
__device__ __forceinline__ u64 f2pk(float lo, float hi) {
    u64 r; asm("mov.b64 %0, {%1, %2};" : "=l"(r) : "f"(lo), "f"(hi)); return r;
}
__device__ __forceinline__ void f2un(u64 v, float& lo, float& hi) {
    asm("mov.b64 {%0, %1}, %2;" : "=f"(lo), "=f"(hi) : "l"(v));
}
__device__ __forceinline__ u64 ffma2(u64 a, u64 b, u64 c) {
    u64 d; asm("fma.rn.f32x2 %0, %1, %2, %3;" : "=l"(d) : "l"(a), "l"(b), "l"(c)); return d;
}
__device__ __forceinline__ u64 fadd2(u64 a, u64 b) {
    u64 d; asm("add.rn.f32x2 %0, %1, %2;" : "=l"(d) : "l"(a), "l"(b)); return d;
}
__device__ __forceinline__ u64 fmul2(u64 a, u64 b) {
    u64 d; asm("mul.rn.f32x2 %0, %1, %2;" : "=l"(d) : "l"(a), "l"(b)); return d;
}

// fp16 staging buffers (device globals; prep kernel fills them in-graph)
__device__ __half w_h[CAP_B * KKA * PSIZE];   // transposed: [j][i][16]
__device__ __half x_h[NX];                    // same layout as x

// Single prep kernel: converts w (with j-major transpose) and x to fp16.
__global__ void convert_kernel(const float* __restrict__ w,
                               const float* __restrict__ x) {
    const int f = blockIdx.x * blockDim.x + threadIdx.x;
    if (f < W4) {
        const int q4 = f & 3;
        const int j  = (f >> 2) & 31;
        const int i  = f >> 7;
        const float4 val = reinterpret_cast<const float4*>(w)[f];
        __half2* dst = reinterpret_cast<__half2*>(w_h + (j * KKA + i) * PSIZE + q4 * 4);
        dst[0] = __floats2half2_rn(val.x, val.y);
        dst[1] = __floats2half2_rn(val.z, val.w);
    } else {
        const int g = f - W4;
        if (g < X4) {
            const float4 val = reinterpret_cast<const float4*>(x)[g];
            __half2* dst = reinterpret_cast<__half2*>(x_h + g * 4);
            dst[0] = __floats2half2_rn(val.x, val.y);
            dst[1] = __floats2half2_rn(val.z, val.w);
        }
    }
}

// Load 16 contiguous halves (32B), widen to fp32 scalars.
__device__ __forceinline__ void load16h(const __half* __restrict__ p, float o[16]) {
    uint4 u0 = *reinterpret_cast<const uint4*>(p);
    uint4 u1 = *reinterpret_cast<const uint4*>(p + 8);
    const unsigned wds[8] = {u0.x, u0.y, u0.z, u0.w, u1.x, u1.y, u1.z, u1.w};
#pragma unroll
    for (int k = 0; k < 8; k++) {
        const float2 f2 = __half22float2(*reinterpret_cast<const __half2*>(&wds[k]));
        o[2 * k]     = f2.x;
        o[2 * k + 1] = f2.y;
    }
}

// Load 16 contiguous halves, widen to 8 packed f32x2 pairs.
__device__ __forceinline__ void load16h2(const __half* __restrict__ p, u64 o[8]) {
    uint4 u0 = *reinterpret_cast<const uint4*>(p);
    uint4 u1 = *reinterpret_cast<const uint4*>(p + 8);
    const unsigned wds[8] = {u0.x, u0.y, u0.z, u0.w, u1.x, u1.y, u1.z, u1.w};
#pragma unroll
    for (int k = 0; k < 8; k++) {
        const float2 f2 = __half22float2(*reinterpret_cast<const __half2*>(&wds[k]));
        o[k] = f2pk(f2.x, f2.y);
    }
}

// Butterfly vector-exchange reduction: 32 lanes each hold t[0..15];
// afterwards lane l holds the lane-sum of component (l & 15). 31 shuffles.
__device__ __forceinline__ void vec_reduce16(float t[16], int lane) {
#pragma unroll
    for (int k = 0; k < 16; k++)
        t[k] += __shfl_xor_sync(FULL, t[k], 16);
    {
        const bool hi = lane & 8;
#pragma unroll
        for (int k = 0; k < 8; k++) {
            float keep = hi ? t[k + 8] : t[k];
            float send = hi ? t[k]     : t[k + 8];
            t[k] = keep + __shfl_xor_sync(FULL, send, 8);
        }
    }
    {
        const bool hi = lane & 4;
#pragma unroll
        for (int k = 0; k < 4; k++) {
            float keep = hi ? t[k + 4] : t[k];
            float send = hi ? t[k]     : t[k + 4];
            t[k] = keep + __shfl_xor_sync(FULL, send, 4);
        }
    }
    {
        const bool hi = lane & 2;
#pragma unroll
        for (int k = 0; k < 2; k++) {
            float keep = hi ? t[k + 2] : t[k];
            float send = hi ? t[k]     : t[k + 2];
            t[k] = keep + __shfl_xor_sync(FULL, send, 2);
        }
    }
    {
        const bool hi = lane & 1;
        float keep = hi ? t[1] : t[0];
        float send = hi ? t[0] : t[1];
        t[0] = keep + __shfl_xor_sync(FULL, send, 1);
    }
}

// Squash on the duplicated 16-vector (lanes l and l+16 both hold comp l&15).
__device__ __forceinline__ float squash16(float s) {
    float n2 = s * s;
#pragma unroll
    for (int off = 8; off >= 1; off >>= 1)
        n2 += __shfl_xor_sync(FULL, n2, off);
    return s * (n2 / (1.f + n2) * rsqrtf(n2 + EPS_SQ));
}

__global__ __launch_bounds__(32, 10) void caps_warp_kernel(
    float* __restrict__ out)         // (2, 15, 15, 512)
{
    const int bid = blockIdx.x;
    const int j   = bid & 31;
    const int n   = bid >> 5;
    const int b   = n / (OH * OW);
    const int rem = n % (OH * OW);
    const int oy  = rem / OW;
    const int ox  = rem % OW;

    const int lane = threadIdx.x;    // = a (input capsule type)

    // Thread owns i_c = c*32 + lane, c = ky*3 + kx.
    const __half* xbase = x_h + ((size_t)((b * 32 + oy * STRIDE) * 32
                                          + ox * STRIDE) * 512 + lane * PSIZE);
    const __half* wbase = w_h + ((size_t)j * KKA + lane) * PSIZE;   // coalesced

    // v2[c][2p+h] packs components (4p+2h, 4p+2h+1) of v[c].
    u64 v2[CPT][8];
#pragma unroll
    for (int c = 0; c < CPT; c++) {
        const int ky = c / 3, kx = c % 3;
        float xm[16];
        u64 wm2[8];   // wm2[2r+h] = (w[4r+2h], w[4r+2h+1])
        load16h(xbase + (size_t)(ky * 32 + kx) * 512, xm);
        load16h2(wbase + (size_t)(c * 32) * PSIZE,    wm2);
#pragma unroll
        for (int p = 0; p < 4; p++) {
            {   // r = 0 initializes
                const u64 xd = f2pk(xm[p * 4], xm[p * 4]);
                v2[c][2 * p]     = fmul2(xd, wm2[0]);
                v2[c][2 * p + 1] = fmul2(xd, wm2[1]);
            }
#pragma unroll
            for (int r = 1; r < 4; r++) {
                const u64 xd = f2pk(xm[p * 4 + r], xm[p * 4 + r]);
                v2[c][2 * p]     = ffma2(xd, wm2[2 * r],     v2[c][2 * p]);
                v2[c][2 * p + 1] = ffma2(xd, wm2[2 * r + 1], v2[c][2 * p + 1]);
            }
        }
    }

    float logit[CPT];
#pragma unroll
    for (int c = 0; c < CPT; c++) logit[c] = 0.f;

    float t[16];
    float pval;   // component (lane&15) of current p

    // ---- iteration 0: logits all zero -> r = 1/288 exactly ----
#pragma unroll
    for (int k = 0; k < 8; k++) {
        u64 s2 = v2[0][k];
#pragma unroll
        for (int c = 1; c < CPT; c++) s2 = fadd2(s2, v2[c][k]);
        f2un(s2, t[2 * k], t[2 * k + 1]);
    }
    vec_reduce16(t, lane);
    pval = squash16(t[0] * (1.0f / (float)KKA));

    // agreement: logit_c += v_c . p  (packed dot, horizontal add at end)
    {
        u64 d2[CPT];
#pragma unroll
        for (int k = 0; k < 8; k++) {
            const float plo = __shfl_sync(FULL, pval, 2 * k);
            const float phi = __shfl_sync(FULL, pval, 2 * k + 1);
            const u64 pq2 = f2pk(plo, phi);
            if (k == 0) {
#pragma unroll
                for (int c = 0; c < CPT; c++) d2[c] = fmul2(v2[c][0], pq2);
            } else {
#pragma unroll
                for (int c = 0; c < CPT; c++) d2[c] = ffma2(v2[c][k], pq2, d2[c]);
            }
        }
#pragma unroll
        for (int c = 0; c < CPT; c++) {
            float dl, dh; f2un(d2[c], dl, dh);
            logit[c] += dl + dh;
        }
    }

    // ---- iterations 1..2 ----
    // Logits are bounded (|logit| <~ 20), so softmax without max-subtraction
    // is safe in fp32 and mathematically identical.
#pragma unroll
    for (int it = 1; it < 3; it++) {
        float e[CPT], z = 0.f;
#pragma unroll
        for (int c = 0; c < CPT; c++) { e[c] = __expf(logit[c]); z += e[c]; }
#pragma unroll
        for (int off = 16; off >= 1; off >>= 1)
            z += __shfl_xor_sync(FULL, z, off);
        const float rZ = __frcp_rn(z);

        // pool with packed weights e_c (scale by 1/Z after the reduction)
        u64 ed[CPT];
#pragma unroll
        for (int c = 0; c < CPT; c++) ed[c] = f2pk(e[c], e[c]);
#pragma unroll
        for (int k = 0; k < 8; k++) {
            u64 s2 = fmul2(ed[0], v2[0][k]);
#pragma unroll
            for (int c = 1; c < CPT; c++) s2 = ffma2(ed[c], v2[c][k], s2);
            f2un(s2, t[2 * k], t[2 * k + 1]);
        }
        vec_reduce16(t, lane);
        pval = squash16(t[0] * rZ);

        if (it < 2) {
            u64 d2[CPT];
#pragma unroll
            for (int k = 0; k < 8; k++) {
                const float plo = __shfl_sync(FULL, pval, 2 * k);
                const float phi = __shfl_sync(FULL, pval, 2 * k + 1);
                const u64 pq2 = f2pk(plo, phi);
                if (k == 0) {
#pragma unroll
                    for (int c = 0; c < CPT; c++) d2[c] = fmul2(v2[c][0], pq2);
                } else {
#pragma unroll
                    for (int c = 0; c < CPT; c++) d2[c] = ffma2(v2[c][k], pq2, d2[c]);
                }
            }
#pragma unroll
            for (int c = 0; c < CPT; c++) {
                float dl, dh; f2un(d2[c], dl, dh);
                logit[c] += dl + dh;
            }
        }
    }

    // ---- output: lanes 0..15 hold p[0..15] ----
    if (lane < 16)
        out[(size_t)n * (CAP_B * PSIZE) + j * PSIZE + lane] = pval;
}

extern "C" void kernel_launch(void* const* d_in, const int* in_sizes, int n_in,
                              void* d_out, int out_size) {
    (void)in_sizes; (void)n_in; (void)out_size;
    const float* x = (const float*)d_in[0];
    const float* w = (const float*)d_in[1];
    float* out = (float*)d_out;

    // 1) single prep launch: fp32 -> fp16 (w transposed to j-major) + x
    convert_kernel<<<(W4 + X4 + 255) / 256, 256>>>(w, x);

    // 2) fused transform + routing, one warp per (n, j)
    dim3 grid(NPOS * CAP_B);   // 14400
    caps_warp_kernel<<<grid, 32>>>(out);
}